// round 14
// baseline (speedup 1.0000x reference)
#include <cuda_runtime.h>
#include <cuda_fp16.h>
#include <cstdint>

// Problem constants
#define T_TOK   4096
#define D_MODEL 1024
#define DFF     2048
#define NROUTED 7
#define BM      128
#define BK      64
#define NTILES_M 104
#define R_MAX   (NTILES_M * BM)
#define NSM     148

// smem tile: 128 rows x 128B data (64 fp16), stride 144B -> conflict-free ldmatrix
#define ROWB   144
#define TILEB  (128 * ROWB)      // 18432 B
#define NSTAGE 4                 // divides KT of both gemms -> per-tile parity resets

// ---------------- scratch (static device globals; no allocations) -------------
__device__ __half d_H[(size_t)R_MAX * DFF];
__device__ __half d_X[(size_t)T_TOK * D_MODEL];
__device__ __half d_wgT[(size_t)8 * DFF * D_MODEL];   // [E][N=DFF][K=D]
__device__ __half d_wuT[(size_t)8 * DFF * D_MODEL];
__device__ __half d_wdT[(size_t)8 * D_MODEL * DFF];   // [E][N=D][K=DFF]
__device__ int    d_tok[R_MAX];
__device__ float  d_wrow[R_MAX];
__device__ int    d_off[8];
__device__ int    d_cnt[NROUTED];
__device__ int    d_cnt2[NROUTED];
__device__ int    d_topi[T_TOK * 2];
__device__ float  d_topw[T_TOK * 2];

// ---------------- helpers ----------------------------------------------------
__device__ __forceinline__ uint32_t smem_u32(const void* p) {
    uint32_t a;
    asm("{ .reg .u64 t; cvta.to.shared.u64 t, %1; cvt.u32.u64 %0, t; }"
        : "=r"(a) : "l"(p));
    return a;
}

__device__ __forceinline__ void hmma(float c[4], const uint32_t a[4], const uint32_t b[2]) {
    asm volatile(
        "mma.sync.aligned.m16n8k16.row.col.f32.f16.f16.f32 "
        "{%0,%1,%2,%3}, {%4,%5,%6,%7}, {%8,%9}, {%0,%1,%2,%3};\n"
        : "+f"(c[0]), "+f"(c[1]), "+f"(c[2]), "+f"(c[3])
        : "r"(a[0]), "r"(a[1]), "r"(a[2]), "r"(a[3]), "r"(b[0]), "r"(b[1]));
}

#define LDSM4(r0, r1, r2, r3, addr) \
    asm volatile("ldmatrix.sync.aligned.m8n8.x4.shared.b16 {%0,%1,%2,%3}, [%4];" \
                 : "=r"(r0), "=r"(r1), "=r"(r2), "=r"(r3) : "r"(addr))

__device__ __forceinline__ void cp16s(uint32_t daddr, const void* src, bool pred) {
    int sz = pred ? 16 : 0;
    asm volatile("cp.async.cg.shared.global [%0], [%1], 16, %2;\n"
                 :: "r"(daddr), "l"(src), "r"(sz));
}
__device__ __forceinline__ void cp_commit() { asm volatile("cp.async.commit_group;\n"); }
__device__ __forceinline__ void cp_waitN(int rem) {
    if (rem >= 3)      asm volatile("cp.async.wait_group 3;\n");
    else if (rem == 2) asm volatile("cp.async.wait_group 2;\n");
    else if (rem == 1) asm volatile("cp.async.wait_group 1;\n");
    else               asm volatile("cp.async.wait_group 0;\n");
}

__device__ __forceinline__ void mbar_init(uint32_t addr, uint32_t cnt) {
    asm volatile("mbarrier.init.shared.b64 [%0], %1;" :: "r"(addr), "r"(cnt) : "memory");
}
__device__ __forceinline__ void mbar_arrive(uint32_t addr) {
    asm volatile("mbarrier.arrive.shared.b64 _, [%0];" :: "r"(addr) : "memory");
}
__device__ __forceinline__ void mbar_wait(uint32_t addr, uint32_t parity) {
    asm volatile(
        "{\n\t.reg .pred P;\n\t"
        "W%=:\n\t"
        "mbarrier.try_wait.parity.acquire.cta.shared::cta.b64 P, [%0], %1, 0x989680;\n\t"
        "@!P bra W%=;\n\t}"
        :: "r"(addr), "r"(parity) : "memory");
}

// ---------------- fast transpose/convert: fp32 [R][C] tile -> fp16 [C][R] ------
__device__ __forceinline__ void tr_tile(const float* __restrict__ s,
                                        __half* __restrict__ d,
                                        int R, int C, int r0, int c0) {
    __shared__ float t[32][66];
    int tid = threadIdx.x;
#pragma unroll
    for (int i = 0; i < 4; i++) {
        int idx = tid + i * 256;
        int r = idx >> 5, c2 = idx & 31;
        float2 v = *(const float2*)(s + (size_t)(r0 + r) * C + c0 + c2 * 2);
        t[r][c2 * 2] = v.x;
        t[r][c2 * 2 + 1] = v.y;
    }
    __syncthreads();
    int c = tid >> 2, q = tid & 3;
    __half h[8];
#pragma unroll
    for (int j = 0; j < 8; j++)
        h[j] = __float2half_rn(t[q * 8 + j][c]);
    *(uint4*)(d + (size_t)(c0 + c) * R + r0 + q * 8) = *(const uint4*)h;
}

__global__ void prep_wgu_kernel(const float* __restrict__ wg,
                                const float* __restrict__ wu) {
    int b = blockIdx.x;                 // 16384 blocks
    int z = b >> 10;
    int ti = b & 1023;
    int e = z & 7;
    const float* s = (z < 8) ? wg : wu;
    __half* d = ((z < 8) ? d_wgT : d_wuT);
    const int R = D_MODEL, C = DFF;
    int cx = ti & 31, ry = ti >> 5;
    tr_tile(s + (size_t)e * R * C, d + (size_t)e * R * C, R, C, ry * 32, cx * 64);
}

__global__ void prep_wd_kernel(const float* __restrict__ wd) {
    int b = blockIdx.x;                 // 8192 blocks
    int e = b >> 10;
    int ti = b & 1023;
    const int R = DFF, C = D_MODEL;
    int cx = ti & 15, ry = ti >> 4;
    tr_tile(wd + (size_t)e * R * C, d_wdT + (size_t)e * R * C, R, C, ry * 32, cx * 64);
}

// ---------------- prep X: init + x convert + router (stream 0) -----------------
__global__ void prep_x_kernel(const float* __restrict__ x,
                              const float* __restrict__ rw,
                              const float* __restrict__ rb,
                              float* __restrict__ out) {
    int tid = threadIdx.x;
    int b = blockIdx.x;
    if (b < 512) {
        int warp = tid >> 5, lane = tid & 31;
        int gw = b * 8 + warp;
        const float* xr = x + (size_t)gw * D_MODEL;
        float acc[NROUTED];
#pragma unroll
        for (int j = 0; j < NROUTED; j++) acc[j] = 0.f;
        for (int k = lane; k < D_MODEL; k += 32) {
            float xv = xr[k];
            const float* w = rw + k * NROUTED;
#pragma unroll
            for (int j = 0; j < NROUTED; j++) acc[j] += xv * w[j];
        }
#pragma unroll
        for (int j = 0; j < NROUTED; j++) {
#pragma unroll
            for (int o = 16; o > 0; o >>= 1)
                acc[j] += __shfl_xor_sync(0xffffffffu, acc[j], o);
        }
        if (lane == 0) {
            float lg[NROUTED];
#pragma unroll
            for (int j = 0; j < NROUTED; j++) lg[j] = acc[j] + rb[j];
            int i1 = 0;
#pragma unroll
            for (int j = 1; j < NROUTED; j++) if (lg[j] > lg[i1]) i1 = j;
            int i2 = (i1 == 0) ? 1 : 0;
#pragma unroll
            for (int j = 0; j < NROUTED; j++)
                if (j != i1 && lg[j] > lg[i2]) i2 = j;
            float m  = fmaxf(lg[i1], lg[i2]);
            float e1 = expf(lg[i1] - m), e2 = expf(lg[i2] - m);
            float s  = e1 + e2;
            d_topi[gw * 2] = i1;  d_topi[gw * 2 + 1] = i2;
            d_topw[gw * 2] = e1 / s;  d_topw[gw * 2 + 1] = e2 / s;
            atomicAdd(&d_cnt[i1], 1);
            atomicAdd(&d_cnt[i2], 1);
        }
    }
    int stride = gridDim.x * blockDim.x;
    int i = b * blockDim.x + tid;
    for (int j = i; j < T_TOK * D_MODEL; j += stride) {
        out[j] = 0.f;
        d_X[j] = __float2half_rn(x[j]);
    }
    for (int j = i; j < R_MAX; j += stride) {
        if (j < T_TOK) { d_tok[j] = j;  d_wrow[j] = 1.f; }
        else           { d_tok[j] = -1; d_wrow[j] = 0.f; }
    }
}

// ---------------- offsets + fill (single block) --------------------------------
__global__ void offsfill_kernel() {
    int tid = threadIdx.x;
    if (tid == 0) {
        int base = T_TOK;
        for (int j = 0; j < NROUTED; j++) {
            d_off[j] = base;
            base += ((d_cnt[j] + BM - 1) / BM) * BM;
            d_cnt[j] = 0;
        }
        d_off[7] = base;
    }
    __syncthreads();
    for (int i = tid; i < T_TOK * 2; i += blockDim.x) {
        int t = i >> 1;
        int e = d_topi[i];
        float w = d_topw[i];
        int p = atomicAdd(&d_cnt2[e], 1);
        int r = d_off[e] + p;
        d_tok[r]  = t;
        d_wrow[r] = w;
    }
    __syncthreads();
    if (tid < NROUTED) d_cnt2[tid] = 0;
}

__device__ __forceinline__ int tile_expert(int row0) {
    if (row0 < T_TOK) return 0;
    int e = 0;
#pragma unroll
    for (int j = 0; j < NROUTED; j++)
        if (row0 >= d_off[j] && row0 < d_off[j + 1]) e = j + 1;
    return e;
}

// ---------------- gemm1: persistent, 8 warps (2m x 4n), warp tile 64x32 --------
#define G1_STG  (3 * TILEB)
#define G1_SMEM (NSTAGE * G1_STG)        // 221184 B

__global__ __launch_bounds__(256, 1) void gemm1_kernel() {
    extern __shared__ char raw[];
    uint32_t base = smem_u32(raw);
    __shared__ int stok[128];
    __shared__ __align__(8) uint64_t s_mb[2 * NSTAGE];

    int tid = threadIdx.x, warp = tid >> 5, lane = tid & 31;
    uint32_t mbF = smem_u32(&s_mb[0]);
    uint32_t mbE = smem_u32(&s_mb[NSTAGE]);
    if (tid < NSTAGE)              mbar_init(mbF + tid * 8, 8);
    else if (tid < 2 * NSTAGE)     mbar_init(mbE + (tid - NSTAGE) * 8, 8);
    __syncthreads();

    int wm = (warp >> 2) * 64, wn = (warp & 3) * 32;

    // ldmatrix intra-tile byte offsets (tile-invariant)
    int arow = 8 * ((lane >> 3) & 1) + (lane & 7);
    int abyt = 16 * (lane >> 4);
    uint32_t aoff[4];
#pragma unroll
    for (int mi = 0; mi < 4; mi++)
        aoff[mi] = (uint32_t)((wm + mi * 16 + arow) * ROWB + abyt);
    int brow = 8 * (lane >> 4) + (lane & 7);
    int bbyt = 16 * ((lane >> 3) & 1);
    uint32_t goff[2], uoff[2];
#pragma unroll
    for (int p = 0; p < 2; p++) {
        uint32_t o = (uint32_t)((wn + p * 16 + brow) * ROWB + bbyt);
        goff[p] = TILEB + o;
        uoff[p] = 2 * TILEB + o;
    }

    const int KT = D_MODEL / BK;            // 16 (divisible by NSTAGE=4)
    const int NT = NTILES_M * (DFF / 128);  // 1664 tiles

    for (int t = blockIdx.x; t < NT; t += gridDim.x) {
        int row0 = (t % NTILES_M) * BM;
        int n0 = (t / NTILES_M) * 128;
        if (row0 >= d_off[7]) continue;
        int e = tile_expert(row0);
        const __half* bg = d_wgT + (size_t)e * DFF * D_MODEL;
        const __half* bu = d_wuT + (size_t)e * DFF * D_MODEL;

        __syncthreads();                    // prior tile fully consumed; stok reusable
        if (tid < 128) stok[tid] = d_tok[row0 + tid];
        __syncthreads();

        int ar[4], ac[4]; const __half* asrc[4]; const __half* gsrc[4]; const __half* usrc[4];
        bool apred[4];
#pragma unroll
        for (int i = 0; i < 4; i++) {
            int f = tid + i * 256;
            ar[i] = f >> 3; ac[i] = f & 7;
            int tok = stok[ar[i]];
            apred[i] = (tok >= 0);
            asrc[i] = d_X + (size_t)(apred[i] ? tok : 0) * D_MODEL + ac[i] * 8;
            gsrc[i] = bg + (size_t)(n0 + ar[i]) * D_MODEL + ac[i] * 8;
            usrc[i] = bu + (size_t)(n0 + ar[i]) * D_MODEL + ac[i] * 8;
        }

        auto issue = [&](int s, int ktile) {
            uint32_t S = base + s * G1_STG;
            int k0 = ktile * BK;
#pragma unroll
            for (int i = 0; i < 4; i++) {
                uint32_t d0 = S + ar[i] * ROWB + ac[i] * 16;
                cp16s(d0,             asrc[i] + (apred[i] ? k0 : 0), apred[i]);
                cp16s(d0 + TILEB,     gsrc[i] + k0, true);
                cp16s(d0 + 2 * TILEB, usrc[i] + k0, true);
            }
            cp_commit();
        };

        float accG[4][4][4], accU[4][4][4];
#pragma unroll
        for (int mi = 0; mi < 4; mi++)
#pragma unroll
            for (int ni = 0; ni < 4; ni++)
#pragma unroll
                for (int r = 0; r < 4; r++) { accG[mi][ni][r] = 0.f; accU[mi][ni][r] = 0.f; }

#pragma unroll
        for (int p = 0; p < NSTAGE; p++) issue(p, p);

        for (int kt = 0; kt < KT; kt++) {
            int s = kt & (NSTAGE - 1);
            uint32_t ph = (uint32_t)((kt >> 2) & 1);
            uint32_t fB = mbF + s * 8, eB = mbE + s * 8;

            cp_waitN(KT - kt - 1);
            __syncwarp();
            if (lane == 0) mbar_arrive(fB);
            mbar_wait(fB, ph);

            uint32_t S = base + s * G1_STG;
#pragma unroll
            for (int ks = 0; ks < 4; ks++) {
                uint32_t a[4][4];
#pragma unroll
                for (int mi = 0; mi < 4; mi++)
                    LDSM4(a[mi][0], a[mi][1], a[mi][2], a[mi][3], S + aoff[mi] + ks * 32);
#pragma unroll
                for (int p = 0; p < 2; p++) {
                    uint32_t g4[4], u4[4];
                    LDSM4(g4[0], g4[1], g4[2], g4[3], S + goff[p] + ks * 32);
                    LDSM4(u4[0], u4[1], u4[2], u4[3], S + uoff[p] + ks * 32);
#pragma unroll
                    for (int mi = 0; mi < 4; mi++) {
                        hmma(accG[mi][2 * p],     a[mi], g4 + 0);
                        hmma(accG[mi][2 * p + 1], a[mi], g4 + 2);
                        hmma(accU[mi][2 * p],     a[mi], u4 + 0);
                        hmma(accU[mi][2 * p + 1], a[mi], u4 + 2);
                    }
                }
            }
            __syncwarp();
            if (lane == 0) mbar_arrive(eB);

            if (kt + NSTAGE < KT) {
                mbar_wait(eB, ph);
                issue(s, kt + NSTAGE);
            }
        }

        // epilogue: H = fp16(silu(g) * u)
#pragma unroll
        for (int mi = 0; mi < 4; mi++)
#pragma unroll
            for (int ni = 0; ni < 4; ni++)
#pragma unroll
                for (int rr = 0; rr < 4; rr++) {
                    int rl = wm + mi * 16 + (lane >> 2) + ((rr >= 2) ? 8 : 0);
                    if (stok[rl] < 0) continue;
                    int col = n0 + wn + ni * 8 + 2 * (lane & 3) + (rr & 1);
                    float g = accG[mi][ni][rr], u = accU[mi][ni][rr];
                    float h = (g / (1.f + __expf(-g))) * u;
                    d_H[(size_t)(row0 + rl) * DFF + col] = __float2half_rn(h);
                }
    }
}

// ---------------- gemm2: persistent, warp tile 64x32, down GEMM + scatter ------
#define G2_STG  (2 * TILEB)
#define G2_SMEM (NSTAGE * G2_STG)        // 147456 B

__global__ __launch_bounds__(256, 1) void gemm2_kernel(float* __restrict__ out) {
    extern __shared__ char raw[];
    uint32_t base = smem_u32(raw);
    __shared__ int stok[128];
    __shared__ float swt[128];
    __shared__ __align__(8) uint64_t s_mb[2 * NSTAGE];

    int tid = threadIdx.x, warp = tid >> 5, lane = tid & 31;
    uint32_t mbF = smem_u32(&s_mb[0]);
    uint32_t mbE = smem_u32(&s_mb[NSTAGE]);
    if (tid < NSTAGE)              mbar_init(mbF + tid * 8, 8);
    else if (tid < 2 * NSTAGE)     mbar_init(mbE + (tid - NSTAGE) * 8, 8);
    __syncthreads();

    int wm = (warp >> 2) * 64, wn = (warp & 3) * 32;

    int arow = 8 * ((lane >> 3) & 1) + (lane & 7);
    int abyt = 16 * (lane >> 4);
    uint32_t aoff[4];
#pragma unroll
    for (int mi = 0; mi < 4; mi++)
        aoff[mi] = (uint32_t)((wm + mi * 16 + arow) * ROWB + abyt);
    int brow = 8 * (lane >> 4) + (lane & 7);
    int bbyt = 16 * ((lane >> 3) & 1);
    uint32_t boff[2];
#pragma unroll
    for (int p = 0; p < 2; p++)
        boff[p] = TILEB + (uint32_t)((wn + p * 16 + brow) * ROWB + bbyt);

    const int KT = DFF / BK;                    // 32 (divisible by 4)
    const int NT = NTILES_M * (D_MODEL / 128);  // 832 tiles

    for (int t = blockIdx.x; t < NT; t += gridDim.x) {
        int row0 = (t % NTILES_M) * BM;
        int n0 = (t / NTILES_M) * 128;
        if (row0 >= d_off[7]) continue;
        int e = tile_expert(row0);
        const __half* bw = d_wdT + (size_t)e * DFF * D_MODEL;

        __syncthreads();
        if (tid < 128) { stok[tid] = d_tok[row0 + tid]; swt[tid] = d_wrow[row0 + tid]; }
        __syncthreads();

        int ar[4], ac[4]; bool apred[4]; const __half* asrc[4]; const __half* bsrc[4];
#pragma unroll
        for (int i = 0; i < 4; i++) {
            int f = tid + i * 256;
            ar[i] = f >> 3; ac[i] = f & 7;
            apred[i] = (stok[ar[i]] >= 0);
            asrc[i] = d_H + (size_t)(row0 + ar[i]) * DFF + ac[i] * 8;
            bsrc[i] = bw + (size_t)(n0 + ar[i]) * DFF + ac[i] * 8;
        }

        auto issue = [&](int s, int ktile) {
            uint32_t S = base + s * G2_STG;
            int k0 = ktile * BK;
#pragma unroll
            for (int i = 0; i < 4; i++) {
                uint32_t d0 = S + ar[i] * ROWB + ac[i] * 16;
                cp16s(d0,         asrc[i] + (apred[i] ? k0 : 0), apred[i]);
                cp16s(d0 + TILEB, bsrc[i] + k0, true);
            }
            cp_commit();
        };

        float acc[4][4][4];
#pragma unroll
        for (int mi = 0; mi < 4; mi++)
#pragma unroll
            for (int ni = 0; ni < 4; ni++)
#pragma unroll
                for (int r = 0; r < 4; r++) acc[mi][ni][r] = 0.f;

#pragma unroll
        for (int p = 0; p < NSTAGE; p++) issue(p, p);

        for (int kt = 0; kt < KT; kt++) {
            int s = kt & (NSTAGE - 1);
            uint32_t ph = (uint32_t)((kt >> 2) & 1);
            uint32_t fB = mbF + s * 8, eB = mbE + s * 8;

            cp_waitN(KT - kt - 1);
            __syncwarp();
            if (lane == 0) mbar_arrive(fB);
            mbar_wait(fB, ph);

            uint32_t S = base + s * G2_STG;
#pragma unroll
            for (int ks = 0; ks < 4; ks++) {
                uint32_t a[4][4];
#pragma unroll
                for (int mi = 0; mi < 4; mi++)
                    LDSM4(a[mi][0], a[mi][1], a[mi][2], a[mi][3], S + aoff[mi] + ks * 32);
#pragma unroll
                for (int p = 0; p < 2; p++) {
                    uint32_t b4[4];
                    LDSM4(b4[0], b4[1], b4[2], b4[3], S + boff[p] + ks * 32);
#pragma unroll
                    for (int mi = 0; mi < 4; mi++) {
                        hmma(acc[mi][2 * p],     a[mi], b4 + 0);
                        hmma(acc[mi][2 * p + 1], a[mi], b4 + 2);
                    }
                }
            }
            __syncwarp();
            if (lane == 0) mbar_arrive(eB);

            if (kt + NSTAGE < KT) {
                mbar_wait(eB, ph);
                issue(s, kt + NSTAGE);
            }
        }

#pragma unroll
        for (int mi = 0; mi < 4; mi++)
#pragma unroll
            for (int ni = 0; ni < 4; ni++)
#pragma unroll
                for (int rr = 0; rr < 4; rr++) {
                    int rl = wm + mi * 16 + (lane >> 2) + ((rr >= 2) ? 8 : 0);
                    int tok = stok[rl];
                    if (tok < 0) continue;
                    int col = n0 + wn + ni * 8 + 2 * (lane & 3) + (rr & 1);
                    atomicAdd(out + (size_t)tok * D_MODEL + col, swt[rl] * acc[mi][ni][rr]);
                }
    }
}

// ---------------- launch: R9 schedule, persistent gemm grids -------------------
extern "C" void kernel_launch(void* const* d_in, const int* in_sizes, int n_in,
                              void* d_out, int out_size) {
    const float* x  = (const float*)d_in[0];
    const float* rw = (const float*)d_in[1];
    const float* rb = (const float*)d_in[2];
    const float* wg = (const float*)d_in[3];
    const float* wu = (const float*)d_in[4];
    const float* wd = (const float*)d_in[5];
    float* out = (float*)d_out;
    (void)in_sizes; (void)n_in; (void)out_size;

    static cudaStream_t s1 = nullptr;
    static cudaEvent_t evFork = nullptr, evGU = nullptr, evWd = nullptr;
    if (!s1) {
        cudaStreamCreateWithFlags(&s1, cudaStreamNonBlocking);
        cudaEventCreateWithFlags(&evFork, cudaEventDisableTiming);
        cudaEventCreateWithFlags(&evGU,   cudaEventDisableTiming);
        cudaEventCreateWithFlags(&evWd,   cudaEventDisableTiming);
        cudaFuncSetAttribute(gemm1_kernel, cudaFuncAttributeMaxDynamicSharedMemorySize, G1_SMEM);
        cudaFuncSetAttribute(gemm2_kernel, cudaFuncAttributeMaxDynamicSharedMemorySize, G2_SMEM);
    }

    cudaEventRecord(evFork, 0);
    cudaStreamWaitEvent(s1, evFork, 0);

    prep_wgu_kernel<<<16384, 256, 0, s1>>>(wg, wu);
    cudaEventRecord(evGU, s1);

    prep_x_kernel<<<1024, 256>>>(x, rw, rb, out);     // stream 0
    offsfill_kernel<<<1, 1024>>>();

    cudaStreamWaitEvent(0, evGU, 0);
    gemm1_kernel<<<NSM, 256, G1_SMEM>>>();            // 4th launch (ncu window)

    prep_wd_kernel<<<8192, 256, 0, s1>>>(wd);         // overlaps gemm1
    cudaEventRecord(evWd, s1);

    cudaStreamWaitEvent(0, evWd, 0);
    gemm2_kernel<<<NSM, 256, G2_SMEM>>>(out);
}

// round 15
// speedup vs baseline: 1.0377x; 1.0377x over previous
#include <cuda_runtime.h>
#include <cuda_fp16.h>
#include <cstdint>

// Problem constants
#define T_TOK   4096
#define D_MODEL 1024
#define DFF     2048
#define NROUTED 7
#define BM      128
#define BK      64
#define NTILES_M 104
#define R_MAX   (NTILES_M * BM)

// smem tile: 128 rows x 128B data (64 fp16), stride 144B -> conflict-free ldmatrix
#define ROWB   144
#define TILEB  (128 * ROWB)      // 18432 B
#define NSTAGE 3

// ---------------- scratch (static device globals; no allocations) -------------
__device__ __half d_H[(size_t)R_MAX * DFF];
__device__ __half d_X[(size_t)T_TOK * D_MODEL];
__device__ __half d_wgT[(size_t)8 * DFF * D_MODEL];   // [E][N=DFF][K=D]
__device__ __half d_wuT[(size_t)8 * DFF * D_MODEL];
__device__ __half d_wdT[(size_t)8 * D_MODEL * DFF];   // [E][N=D][K=DFF]
__device__ int    d_tok[R_MAX];
__device__ float  d_wrow[R_MAX];
__device__ int    d_off[8];
__device__ int    d_cnt[NROUTED];
__device__ int    d_cnt2[NROUTED];
__device__ int    d_topi[T_TOK * 2];
__device__ float  d_topw[T_TOK * 2];

// ---------------- helpers ----------------------------------------------------
__device__ __forceinline__ uint32_t smem_u32(const void* p) {
    uint32_t a;
    asm("{ .reg .u64 t; cvta.to.shared.u64 t, %1; cvt.u32.u64 %0, t; }"
        : "=r"(a) : "l"(p));
    return a;
}

__device__ __forceinline__ void hmma(float c[4], const uint32_t a[4], const uint32_t b[2]) {
    asm volatile(
        "mma.sync.aligned.m16n8k16.row.col.f32.f16.f16.f32 "
        "{%0,%1,%2,%3}, {%4,%5,%6,%7}, {%8,%9}, {%0,%1,%2,%3};\n"
        : "+f"(c[0]), "+f"(c[1]), "+f"(c[2]), "+f"(c[3])
        : "r"(a[0]), "r"(a[1]), "r"(a[2]), "r"(a[3]), "r"(b[0]), "r"(b[1]));
}

#define LDSM4(r0, r1, r2, r3, addr) \
    asm volatile("ldmatrix.sync.aligned.m8n8.x4.shared.b16 {%0,%1,%2,%3}, [%4];" \
                 : "=r"(r0), "=r"(r1), "=r"(r2), "=r"(r3) : "r"(addr))

__device__ __forceinline__ void cp16s(uint32_t daddr, const void* src, bool pred) {
    int sz = pred ? 16 : 0;
    asm volatile("cp.async.cg.shared.global [%0], [%1], 16, %2;\n"
                 :: "r"(daddr), "l"(src), "r"(sz));
}
__device__ __forceinline__ void cp_commit() { asm volatile("cp.async.commit_group;\n"); }
__device__ __forceinline__ void cp_wait2()  { asm volatile("cp.async.wait_group 2;\n"); }
__device__ __forceinline__ void cp_wait1()  { asm volatile("cp.async.wait_group 1;\n"); }
__device__ __forceinline__ void cp_wait0()  { asm volatile("cp.async.wait_group 0;\n"); }

__device__ __forceinline__ void mbar_init(uint32_t addr, uint32_t cnt) {
    asm volatile("mbarrier.init.shared.b64 [%0], %1;" :: "r"(addr), "r"(cnt) : "memory");
}
__device__ __forceinline__ void mbar_arrive(uint32_t addr) {
    asm volatile("mbarrier.arrive.shared.b64 _, [%0];" :: "r"(addr) : "memory");
}
__device__ __forceinline__ void mbar_wait(uint32_t addr, uint32_t parity) {
    asm volatile(
        "{\n\t.reg .pred P;\n\t"
        "W%=:\n\t"
        "mbarrier.try_wait.parity.acquire.cta.shared::cta.b64 P, [%0], %1, 0x989680;\n\t"
        "@!P bra W%=;\n\t}"
        :: "r"(addr), "r"(parity) : "memory");
}

// ---------------- coalesced transpose/convert: fp32 [R][C] -> fp16 [C][R] ------
// tile = 128 rows x 32 cols: output rows receive 256B contiguous (full coalescing)
__device__ __forceinline__ void tr_tile128(const float* __restrict__ s,
                                           __half* __restrict__ d,
                                           int R, int C, int r0, int c0) {
    __shared__ float t[128][33];
    int tid = threadIdx.x;
    // load 128x32 fp32: 1024 float4-chunks, 4 per thread; 128B contiguous per row
#pragma unroll
    for (int i = 0; i < 4; i++) {
        int ch = tid + i * 256;
        int r = ch >> 3, c4 = (ch & 7) * 4;
        float4 v = *(const float4*)(s + (size_t)(r0 + r) * C + c0 + c4);
        t[r][c4] = v.x; t[r][c4 + 1] = v.y; t[r][c4 + 2] = v.z; t[r][c4 + 3] = v.w;
    }
    __syncthreads();
    // store 32 output rows x 128 halves (256B contiguous): 512 uint4-chunks, 2/thread
#pragma unroll
    for (int i = 0; i < 2; i++) {
        int ch = tid + i * 256;
        int c = ch >> 4, q = ch & 15;
        __half h[8];
#pragma unroll
        for (int j = 0; j < 8; j++)
            h[j] = __float2half_rn(t[q * 8 + j][c]);
        *(uint4*)(d + (size_t)(c0 + c) * R + r0 + q * 8) = *(const uint4*)h;
    }
}

// wg + wu: [E][1024][2048] -> [E][2048][1024]; 8 r-tiles x 64 c-tiles = 512/matrix
__global__ void prep_wgu_kernel(const float* __restrict__ wg,
                                const float* __restrict__ wu) {
    int b = blockIdx.x;                 // 8192 blocks
    int z = b >> 9;                     // 0..15
    int ti = b & 511;
    int e = z & 7;
    const float* s = (z < 8) ? wg : wu;
    __half* d = ((z < 8) ? d_wgT : d_wuT);
    const int R = D_MODEL, C = DFF;
    int cx = ti & 63, ry = ti >> 6;     // 64 c-tiles x 8 r-tiles
    tr_tile128(s + (size_t)e * R * C, d + (size_t)e * R * C, R, C, ry * 128, cx * 32);
}

// wd: [E][2048][1024] -> [E][1024][2048]; 16 r-tiles x 32 c-tiles = 512/expert
__global__ void prep_wd_kernel(const float* __restrict__ wd) {
    int b = blockIdx.x;                 // 4096 blocks
    int e = b >> 9;
    int ti = b & 511;
    const int R = DFF, C = D_MODEL;
    int cx = ti & 31, ry = ti >> 5;     // 32 c-tiles x 16 r-tiles
    tr_tile128(wd + (size_t)e * R * C, d_wdT + (size_t)e * R * C, R, C, ry * 128, cx * 32);
}

// ---------------- prep X: init + x convert + router (stream 0) -----------------
__global__ void prep_x_kernel(const float* __restrict__ x,
                              const float* __restrict__ rw,
                              const float* __restrict__ rb,
                              float* __restrict__ out) {
    int tid = threadIdx.x;
    int b = blockIdx.x;
    if (b < 512) {
        int warp = tid >> 5, lane = tid & 31;
        int gw = b * 8 + warp;
        const float* xr = x + (size_t)gw * D_MODEL;
        float acc[NROUTED];
#pragma unroll
        for (int j = 0; j < NROUTED; j++) acc[j] = 0.f;
        for (int k = lane; k < D_MODEL; k += 32) {
            float xv = xr[k];
            const float* w = rw + k * NROUTED;
#pragma unroll
            for (int j = 0; j < NROUTED; j++) acc[j] += xv * w[j];
        }
#pragma unroll
        for (int j = 0; j < NROUTED; j++) {
#pragma unroll
            for (int o = 16; o > 0; o >>= 1)
                acc[j] += __shfl_xor_sync(0xffffffffu, acc[j], o);
        }
        if (lane == 0) {
            float lg[NROUTED];
#pragma unroll
            for (int j = 0; j < NROUTED; j++) lg[j] = acc[j] + rb[j];
            int i1 = 0;
#pragma unroll
            for (int j = 1; j < NROUTED; j++) if (lg[j] > lg[i1]) i1 = j;
            int i2 = (i1 == 0) ? 1 : 0;
#pragma unroll
            for (int j = 0; j < NROUTED; j++)
                if (j != i1 && lg[j] > lg[i2]) i2 = j;
            float m  = fmaxf(lg[i1], lg[i2]);
            float e1 = expf(lg[i1] - m), e2 = expf(lg[i2] - m);
            float s  = e1 + e2;
            d_topi[gw * 2] = i1;  d_topi[gw * 2 + 1] = i2;
            d_topw[gw * 2] = e1 / s;  d_topw[gw * 2 + 1] = e2 / s;
            atomicAdd(&d_cnt[i1], 1);
            atomicAdd(&d_cnt[i2], 1);
        }
    }
    int stride = gridDim.x * blockDim.x;
    int i = b * blockDim.x + tid;
    for (int j = i; j < T_TOK * D_MODEL; j += stride) {
        out[j] = 0.f;
        d_X[j] = __float2half_rn(x[j]);
    }
    for (int j = i; j < R_MAX; j += stride) {
        if (j < T_TOK) { d_tok[j] = j;  d_wrow[j] = 1.f; }
        else           { d_tok[j] = -1; d_wrow[j] = 0.f; }
    }
}

// ---------------- offsets + fill (single block) --------------------------------
__global__ void offsfill_kernel() {
    int tid = threadIdx.x;
    if (tid == 0) {
        int base = T_TOK;
        for (int j = 0; j < NROUTED; j++) {
            d_off[j] = base;
            base += ((d_cnt[j] + BM - 1) / BM) * BM;
            d_cnt[j] = 0;
        }
        d_off[7] = base;
    }
    __syncthreads();
    for (int i = tid; i < T_TOK * 2; i += blockDim.x) {
        int t = i >> 1;
        int e = d_topi[i];
        float w = d_topw[i];
        int p = atomicAdd(&d_cnt2[e], 1);
        int r = d_off[e] + p;
        d_tok[r]  = t;
        d_wrow[r] = w;
    }
    __syncthreads();
    if (tid < NROUTED) d_cnt2[tid] = 0;
}

__device__ __forceinline__ int tile_expert(int row0) {
    if (row0 < T_TOK) return 0;
    int e = 0;
#pragma unroll
    for (int j = 0; j < NROUTED; j++)
        if (row0 >= d_off[j] && row0 < d_off[j + 1]) e = j + 1;
    return e;
}

// ---------------- gemm1: 256 thr, 8 warps (2m x 4n), warp tile 64x32 -----------
#define G1_STG  (3 * TILEB)
#define G1_SMEM (NSTAGE * G1_STG)        // 165888 B

__global__ __launch_bounds__(256, 1) void gemm1_kernel() {
    int row0 = blockIdx.x * BM;
    if (row0 >= d_off[7]) return;
    int e = tile_expert(row0);
    const __half* bg = d_wgT + (size_t)e * DFF * D_MODEL;
    const __half* bu = d_wuT + (size_t)e * DFF * D_MODEL;
    int n0 = blockIdx.y * 128;

    extern __shared__ char raw[];
    uint32_t base = smem_u32(raw);
    __shared__ int stok[128];
    __shared__ __align__(8) uint64_t s_mb[2 * NSTAGE];

    int tid = threadIdx.x, warp = tid >> 5, lane = tid & 31;
    if (tid < 128) stok[tid] = d_tok[row0 + tid];
    uint32_t mbF = smem_u32(&s_mb[0]);
    uint32_t mbE = smem_u32(&s_mb[NSTAGE]);
    if (tid < NSTAGE)              mbar_init(mbF + tid * 8, 8);
    else if (tid < 2 * NSTAGE)     mbar_init(mbE + (tid - NSTAGE) * 8, 8);
    __syncthreads();

    int wm = (warp >> 2) * 64, wn = (warp & 3) * 32;

    int ar[4], ac[4]; const __half* asrc[4]; const __half* gsrc[4]; const __half* usrc[4];
    bool apred[4];
#pragma unroll
    for (int i = 0; i < 4; i++) {
        int f = tid + i * 256;
        ar[i] = f >> 3; ac[i] = f & 7;
        int tok = stok[ar[i]];
        apred[i] = (tok >= 0);
        asrc[i] = d_X + (size_t)(apred[i] ? tok : 0) * D_MODEL + ac[i] * 8;
        gsrc[i] = bg + (size_t)(n0 + ar[i]) * D_MODEL + ac[i] * 8;
        usrc[i] = bu + (size_t)(n0 + ar[i]) * D_MODEL + ac[i] * 8;
    }

    auto issue = [&](int s, int ktile) {
        uint32_t S = base + s * G1_STG;
        int k0 = ktile * BK;
#pragma unroll
        for (int i = 0; i < 4; i++) {
            uint32_t d0 = S + ar[i] * ROWB + ac[i] * 16;
            cp16s(d0,             asrc[i] + (apred[i] ? k0 : 0), apred[i]);
            cp16s(d0 + TILEB,     gsrc[i] + k0, true);
            cp16s(d0 + 2 * TILEB, usrc[i] + k0, true);
        }
        cp_commit();
    };

    int arow = 8 * ((lane >> 3) & 1) + (lane & 7);
    int abyt = 16 * (lane >> 4);
    uint32_t aoff[4];
#pragma unroll
    for (int mi = 0; mi < 4; mi++)
        aoff[mi] = (uint32_t)((wm + mi * 16 + arow) * ROWB + abyt);
    int brow = 8 * (lane >> 4) + (lane & 7);
    int bbyt = 16 * ((lane >> 3) & 1);
    uint32_t goff[2], uoff[2];
#pragma unroll
    for (int p = 0; p < 2; p++) {
        uint32_t o = (uint32_t)((wn + p * 16 + brow) * ROWB + bbyt);
        goff[p] = TILEB + o;
        uoff[p] = 2 * TILEB + o;
    }

    float accG[4][4][4], accU[4][4][4];
#pragma unroll
    for (int mi = 0; mi < 4; mi++)
#pragma unroll
        for (int ni = 0; ni < 4; ni++)
#pragma unroll
            for (int r = 0; r < 4; r++) { accG[mi][ni][r] = 0.f; accU[mi][ni][r] = 0.f; }

    const int KT = D_MODEL / BK;   // 16
#pragma unroll
    for (int p = 0; p < NSTAGE; p++) issue(p, p);

    for (int kt = 0; kt < KT; kt++) {
        int s = kt % NSTAGE;
        uint32_t ph = (uint32_t)((kt / NSTAGE) & 1);
        uint32_t fB = mbF + s * 8, eB = mbE + s * 8;

        if (kt < KT - 2) cp_wait2(); else if (kt == KT - 2) cp_wait1(); else cp_wait0();
        __syncwarp();
        if (lane == 0) mbar_arrive(fB);
        mbar_wait(fB, ph);

        uint32_t S = base + s * G1_STG;
#pragma unroll
        for (int ks = 0; ks < 4; ks++) {
            uint32_t a[4][4];
#pragma unroll
            for (int mi = 0; mi < 4; mi++)
                LDSM4(a[mi][0], a[mi][1], a[mi][2], a[mi][3], S + aoff[mi] + ks * 32);
#pragma unroll
            for (int p = 0; p < 2; p++) {
                uint32_t g4[4], u4[4];
                LDSM4(g4[0], g4[1], g4[2], g4[3], S + goff[p] + ks * 32);
                LDSM4(u4[0], u4[1], u4[2], u4[3], S + uoff[p] + ks * 32);
#pragma unroll
                for (int mi = 0; mi < 4; mi++) {
                    hmma(accG[mi][2 * p],     a[mi], g4 + 0);
                    hmma(accG[mi][2 * p + 1], a[mi], g4 + 2);
                    hmma(accU[mi][2 * p],     a[mi], u4 + 0);
                    hmma(accU[mi][2 * p + 1], a[mi], u4 + 2);
                }
            }
        }
        __syncwarp();
        if (lane == 0) mbar_arrive(eB);

        if (kt + NSTAGE < KT) {
            mbar_wait(eB, ph);
            issue(s, kt + NSTAGE);
        }
    }

#pragma unroll
    for (int mi = 0; mi < 4; mi++)
#pragma unroll
        for (int ni = 0; ni < 4; ni++)
#pragma unroll
            for (int rr = 0; rr < 4; rr++) {
                int rl = wm + mi * 16 + (lane >> 2) + ((rr >= 2) ? 8 : 0);
                if (stok[rl] < 0) continue;
                int col = n0 + wn + ni * 8 + 2 * (lane & 3) + (rr & 1);
                float g = accG[mi][ni][rr], u = accU[mi][ni][rr];
                float h = (g / (1.f + __expf(-g))) * u;
                d_H[(size_t)(row0 + rl) * DFF + col] = __float2half_rn(h);
            }
}

// ---------------- gemm2: 256 thr, warp tile 64x32, down GEMM + scatter ---------
#define G2_STG  (2 * TILEB)
#define G2_SMEM (NSTAGE * G2_STG)        // 110592 B

__global__ __launch_bounds__(256, 1) void gemm2_kernel(float* __restrict__ out) {
    int row0 = blockIdx.x * BM;
    if (row0 >= d_off[7]) return;
    int e = tile_expert(row0);
    const __half* bw = d_wdT + (size_t)e * DFF * D_MODEL;
    int n0 = blockIdx.y * 128;

    extern __shared__ char raw[];
    uint32_t base = smem_u32(raw);
    __shared__ int stok[128];
    __shared__ float swt[128];
    __shared__ __align__(8) uint64_t s_mb[2 * NSTAGE];

    int tid = threadIdx.x, warp = tid >> 5, lane = tid & 31;
    if (tid < 128) { stok[tid] = d_tok[row0 + tid]; swt[tid] = d_wrow[row0 + tid]; }
    uint32_t mbF = smem_u32(&s_mb[0]);
    uint32_t mbE = smem_u32(&s_mb[NSTAGE]);
    if (tid < NSTAGE)              mbar_init(mbF + tid * 8, 8);
    else if (tid < 2 * NSTAGE)     mbar_init(mbE + (tid - NSTAGE) * 8, 8);
    __syncthreads();

    int wm = (warp >> 2) * 64, wn = (warp & 3) * 32;

    int ar[4], ac[4]; bool apred[4]; const __half* asrc[4]; const __half* bsrc[4];
#pragma unroll
    for (int i = 0; i < 4; i++) {
        int f = tid + i * 256;
        ar[i] = f >> 3; ac[i] = f & 7;
        apred[i] = (stok[ar[i]] >= 0);
        asrc[i] = d_H + (size_t)(row0 + ar[i]) * DFF + ac[i] * 8;
        bsrc[i] = bw + (size_t)(n0 + ar[i]) * DFF + ac[i] * 8;
    }

    auto issue = [&](int s, int ktile) {
        uint32_t S = base + s * G2_STG;
        int k0 = ktile * BK;
#pragma unroll
        for (int i = 0; i < 4; i++) {
            uint32_t d0 = S + ar[i] * ROWB + ac[i] * 16;
            cp16s(d0,         asrc[i] + (apred[i] ? k0 : 0), apred[i]);
            cp16s(d0 + TILEB, bsrc[i] + k0, true);
        }
        cp_commit();
    };

    int arow = 8 * ((lane >> 3) & 1) + (lane & 7);
    int abyt = 16 * (lane >> 4);
    uint32_t aoff[4];
#pragma unroll
    for (int mi = 0; mi < 4; mi++)
        aoff[mi] = (uint32_t)((wm + mi * 16 + arow) * ROWB + abyt);
    int brow = 8 * (lane >> 4) + (lane & 7);
    int bbyt = 16 * ((lane >> 3) & 1);
    uint32_t boff[2];
#pragma unroll
    for (int p = 0; p < 2; p++)
        boff[p] = TILEB + (uint32_t)((wn + p * 16 + brow) * ROWB + bbyt);

    float acc[4][4][4];
#pragma unroll
    for (int mi = 0; mi < 4; mi++)
#pragma unroll
        for (int ni = 0; ni < 4; ni++)
#pragma unroll
            for (int r = 0; r < 4; r++) acc[mi][ni][r] = 0.f;

    const int KT = DFF / BK;   // 32
#pragma unroll
    for (int p = 0; p < NSTAGE; p++) issue(p, p);

    for (int kt = 0; kt < KT; kt++) {
        int s = kt % NSTAGE;
        uint32_t ph = (uint32_t)((kt / NSTAGE) & 1);
        uint32_t fB = mbF + s * 8, eB = mbE + s * 8;

        if (kt < KT - 2) cp_wait2(); else if (kt == KT - 2) cp_wait1(); else cp_wait0();
        __syncwarp();
        if (lane == 0) mbar_arrive(fB);
        mbar_wait(fB, ph);

        uint32_t S = base + s * G2_STG;
#pragma unroll
        for (int ks = 0; ks < 4; ks++) {
            uint32_t a[4][4];
#pragma unroll
            for (int mi = 0; mi < 4; mi++)
                LDSM4(a[mi][0], a[mi][1], a[mi][2], a[mi][3], S + aoff[mi] + ks * 32);
#pragma unroll
            for (int p = 0; p < 2; p++) {
                uint32_t b4[4];
                LDSM4(b4[0], b4[1], b4[2], b4[3], S + boff[p] + ks * 32);
#pragma unroll
                for (int mi = 0; mi < 4; mi++) {
                    hmma(acc[mi][2 * p],     a[mi], b4 + 0);
                    hmma(acc[mi][2 * p + 1], a[mi], b4 + 2);
                }
            }
        }
        __syncwarp();
        if (lane == 0) mbar_arrive(eB);

        if (kt + NSTAGE < KT) {
            mbar_wait(eB, ph);
            issue(s, kt + NSTAGE);
        }
    }

#pragma unroll
    for (int mi = 0; mi < 4; mi++)
#pragma unroll
        for (int ni = 0; ni < 4; ni++)
#pragma unroll
            for (int rr = 0; rr < 4; rr++) {
                int rl = wm + mi * 16 + (lane >> 2) + ((rr >= 2) ? 8 : 0);
                int tok = stok[rl];
                if (tok < 0) continue;
                int col = n0 + wn + ni * 8 + 2 * (lane & 3) + (rr & 1);
                atomicAdd(out + (size_t)tok * D_MODEL + col, swt[rl] * acc[mi][ni][rr]);
            }
}

// ---------------- launch: R13 schedule -----------------------------------------
extern "C" void kernel_launch(void* const* d_in, const int* in_sizes, int n_in,
                              void* d_out, int out_size) {
    const float* x  = (const float*)d_in[0];
    const float* rw = (const float*)d_in[1];
    const float* rb = (const float*)d_in[2];
    const float* wg = (const float*)d_in[3];
    const float* wu = (const float*)d_in[4];
    const float* wd = (const float*)d_in[5];
    float* out = (float*)d_out;
    (void)in_sizes; (void)n_in; (void)out_size;

    static cudaStream_t s1 = nullptr;
    static cudaEvent_t evFork = nullptr, evGU = nullptr, evWd = nullptr;
    if (!s1) {
        cudaStreamCreateWithFlags(&s1, cudaStreamNonBlocking);
        cudaEventCreateWithFlags(&evFork, cudaEventDisableTiming);
        cudaEventCreateWithFlags(&evGU,   cudaEventDisableTiming);
        cudaEventCreateWithFlags(&evWd,   cudaEventDisableTiming);
        cudaFuncSetAttribute(gemm1_kernel, cudaFuncAttributeMaxDynamicSharedMemorySize, G1_SMEM);
        cudaFuncSetAttribute(gemm2_kernel, cudaFuncAttributeMaxDynamicSharedMemorySize, G2_SMEM);
    }

    cudaEventRecord(evFork, 0);
    cudaStreamWaitEvent(s1, evFork, 0);

    prep_wgu_kernel<<<8192, 256, 0, s1>>>(wg, wu);
    cudaEventRecord(evGU, s1);

    prep_x_kernel<<<1024, 256>>>(x, rw, rb, out);     // stream 0
    offsfill_kernel<<<1, 1024>>>();

    cudaStreamWaitEvent(0, evGU, 0);
    gemm1_kernel<<<dim3(NTILES_M, DFF / 128), 256, G1_SMEM>>>();   // 4th launch (ncu)

    prep_wd_kernel<<<4096, 256, 0, s1>>>(wd);         // overlaps gemm1
    cudaEventRecord(evWd, s1);

    cudaStreamWaitEvent(0, evWd, 0);
    gemm2_kernel<<<dim3(NTILES_M, D_MODEL / 128), 256, G2_SMEM>>>(out);
}

// round 16
// speedup vs baseline: 1.0398x; 1.0020x over previous
#include <cuda_runtime.h>
#include <cuda_fp16.h>
#include <cstdint>

// Problem constants
#define T_TOK   4096
#define D_MODEL 1024
#define DFF     2048
#define NROUTED 7
#define BM      128
#define BK      64
#define NTILES_M 104
#define R_MAX   (NTILES_M * BM)

// smem tile: 128 rows x 128B data (64 fp16), stride 144B -> conflict-free ldmatrix
#define ROWB   144
#define TILEB  (128 * ROWB)      // 18432 B
#define NSTAGE 3

// ---------------- scratch (static device globals; no allocations) -------------
__device__ __half d_H[(size_t)R_MAX * DFF];
__device__ __half d_X[(size_t)T_TOK * D_MODEL];
__device__ __half d_wgT[(size_t)8 * DFF * D_MODEL];   // [E][N=DFF][K=D]
__device__ __half d_wuT[(size_t)8 * DFF * D_MODEL];
__device__ __half d_wdT[(size_t)8 * D_MODEL * DFF];   // [E][N=D][K=DFF]
__device__ int    d_tok[R_MAX];
__device__ float  d_wrow[R_MAX];
__device__ int    d_off[8];
__device__ int    d_cnt[NROUTED];
__device__ int    d_cnt2[NROUTED];
__device__ int    d_topi[T_TOK * 2];
__device__ float  d_topw[T_TOK * 2];

// ---------------- helpers ----------------------------------------------------
__device__ __forceinline__ uint32_t smem_u32(const void* p) {
    uint32_t a;
    asm("{ .reg .u64 t; cvta.to.shared.u64 t, %1; cvt.u32.u64 %0, t; }"
        : "=r"(a) : "l"(p));
    return a;
}

__device__ __forceinline__ void hmma(float c[4], const uint32_t a[4], const uint32_t b[2]) {
    asm volatile(
        "mma.sync.aligned.m16n8k16.row.col.f32.f16.f16.f32 "
        "{%0,%1,%2,%3}, {%4,%5,%6,%7}, {%8,%9}, {%0,%1,%2,%3};\n"
        : "+f"(c[0]), "+f"(c[1]), "+f"(c[2]), "+f"(c[3])
        : "r"(a[0]), "r"(a[1]), "r"(a[2]), "r"(a[3]), "r"(b[0]), "r"(b[1]));
}

#define LDSM4(r0, r1, r2, r3, addr) \
    asm volatile("ldmatrix.sync.aligned.m8n8.x4.shared.b16 {%0,%1,%2,%3}, [%4];" \
                 : "=r"(r0), "=r"(r1), "=r"(r2), "=r"(r3) : "r"(addr))

__device__ __forceinline__ void cp16s(uint32_t daddr, const void* src, bool pred) {
    int sz = pred ? 16 : 0;
    asm volatile("cp.async.cg.shared.global [%0], [%1], 16, %2;\n"
                 :: "r"(daddr), "l"(src), "r"(sz));
}
__device__ __forceinline__ void cp_commit() { asm volatile("cp.async.commit_group;\n"); }
__device__ __forceinline__ void cp_wait2()  { asm volatile("cp.async.wait_group 2;\n"); }
__device__ __forceinline__ void cp_wait1()  { asm volatile("cp.async.wait_group 1;\n"); }
__device__ __forceinline__ void cp_wait0()  { asm volatile("cp.async.wait_group 0;\n"); }

__device__ __forceinline__ void mbar_init(uint32_t addr, uint32_t cnt) {
    asm volatile("mbarrier.init.shared.b64 [%0], %1;" :: "r"(addr), "r"(cnt) : "memory");
}
__device__ __forceinline__ void mbar_arrive(uint32_t addr) {
    asm volatile("mbarrier.arrive.shared.b64 _, [%0];" :: "r"(addr) : "memory");
}
__device__ __forceinline__ void mbar_wait(uint32_t addr, uint32_t parity) {
    asm volatile(
        "{\n\t.reg .pred P;\n\t"
        "W%=:\n\t"
        "mbarrier.try_wait.parity.acquire.cta.shared::cta.b64 P, [%0], %1, 0x989680;\n\t"
        "@!P bra W%=;\n\t}"
        :: "r"(addr), "r"(parity) : "memory");
}

// ---------------- coalesced transpose/convert: fp32 [R][C] -> fp16 [C][R] ------
__device__ __forceinline__ void tr_tile128(const float* __restrict__ s,
                                           __half* __restrict__ d,
                                           int R, int C, int r0, int c0) {
    __shared__ float t[128][33];
    int tid = threadIdx.x;
#pragma unroll
    for (int i = 0; i < 4; i++) {
        int ch = tid + i * 256;
        int r = ch >> 3, c4 = (ch & 7) * 4;
        float4 v = *(const float4*)(s + (size_t)(r0 + r) * C + c0 + c4);
        t[r][c4] = v.x; t[r][c4 + 1] = v.y; t[r][c4 + 2] = v.z; t[r][c4 + 3] = v.w;
    }
    __syncthreads();
#pragma unroll
    for (int i = 0; i < 2; i++) {
        int ch = tid + i * 256;
        int c = ch >> 4, q = ch & 15;
        __half h[8];
#pragma unroll
        for (int j = 0; j < 8; j++)
            h[j] = __float2half_rn(t[q * 8 + j][c]);
        *(uint4*)(d + (size_t)(c0 + c) * R + r0 + q * 8) = *(const uint4*)h;
    }
}

__global__ void prep_wgu_kernel(const float* __restrict__ wg,
                                const float* __restrict__ wu) {
    int b = blockIdx.x;                 // 8192 blocks
    int z = b >> 9;
    int ti = b & 511;
    int e = z & 7;
    const float* s = (z < 8) ? wg : wu;
    __half* d = ((z < 8) ? d_wgT : d_wuT);
    const int R = D_MODEL, C = DFF;
    int cx = ti & 63, ry = ti >> 6;
    tr_tile128(s + (size_t)e * R * C, d + (size_t)e * R * C, R, C, ry * 128, cx * 32);
}

__global__ void prep_wd_kernel(const float* __restrict__ wd) {
    int b = blockIdx.x;                 // 4096 blocks
    int e = b >> 9;
    int ti = b & 511;
    const int R = DFF, C = D_MODEL;
    int cx = ti & 31, ry = ti >> 5;
    tr_tile128(wd + (size_t)e * R * C, d_wdT + (size_t)e * R * C, R, C, ry * 128, cx * 32);
}

// ---------------- prep X: init + x convert + router (stream 0) -----------------
__global__ void prep_x_kernel(const float* __restrict__ x,
                              const float* __restrict__ rw,
                              const float* __restrict__ rb,
                              float* __restrict__ out) {
    int tid = threadIdx.x;
    int b = blockIdx.x;
    if (b < 512) {
        int warp = tid >> 5, lane = tid & 31;
        int gw = b * 8 + warp;
        const float* xr = x + (size_t)gw * D_MODEL;
        float acc[NROUTED];
#pragma unroll
        for (int j = 0; j < NROUTED; j++) acc[j] = 0.f;
        for (int k = lane; k < D_MODEL; k += 32) {
            float xv = xr[k];
            const float* w = rw + k * NROUTED;
#pragma unroll
            for (int j = 0; j < NROUTED; j++) acc[j] += xv * w[j];
        }
#pragma unroll
        for (int j = 0; j < NROUTED; j++) {
#pragma unroll
            for (int o = 16; o > 0; o >>= 1)
                acc[j] += __shfl_xor_sync(0xffffffffu, acc[j], o);
        }
        if (lane == 0) {
            float lg[NROUTED];
#pragma unroll
            for (int j = 0; j < NROUTED; j++) lg[j] = acc[j] + rb[j];
            int i1 = 0;
#pragma unroll
            for (int j = 1; j < NROUTED; j++) if (lg[j] > lg[i1]) i1 = j;
            int i2 = (i1 == 0) ? 1 : 0;
#pragma unroll
            for (int j = 0; j < NROUTED; j++)
                if (j != i1 && lg[j] > lg[i2]) i2 = j;
            float m  = fmaxf(lg[i1], lg[i2]);
            float e1 = expf(lg[i1] - m), e2 = expf(lg[i2] - m);
            float s  = e1 + e2;
            d_topi[gw * 2] = i1;  d_topi[gw * 2 + 1] = i2;
            d_topw[gw * 2] = e1 / s;  d_topw[gw * 2 + 1] = e2 / s;
            atomicAdd(&d_cnt[i1], 1);
            atomicAdd(&d_cnt[i2], 1);
        }
    }
    int stride = gridDim.x * blockDim.x;
    int i = b * blockDim.x + tid;
    for (int j = i; j < T_TOK * D_MODEL; j += stride) {
        out[j] = 0.f;
        d_X[j] = __float2half_rn(x[j]);
    }
    for (int j = i; j < R_MAX; j += stride) {
        if (j < T_TOK) { d_tok[j] = j;  d_wrow[j] = 1.f; }
        else           { d_tok[j] = -1; d_wrow[j] = 0.f; }
    }
}

// ---------------- offsets + fill (single block) --------------------------------
__global__ void offsfill_kernel() {
    int tid = threadIdx.x;
    if (tid == 0) {
        int base = T_TOK;
        for (int j = 0; j < NROUTED; j++) {
            d_off[j] = base;
            base += ((d_cnt[j] + BM - 1) / BM) * BM;
            d_cnt[j] = 0;
        }
        d_off[7] = base;
    }
    __syncthreads();
    for (int i = tid; i < T_TOK * 2; i += blockDim.x) {
        int t = i >> 1;
        int e = d_topi[i];
        float w = d_topw[i];
        int p = atomicAdd(&d_cnt2[e], 1);
        int r = d_off[e] + p;
        d_tok[r]  = t;
        d_wrow[r] = w;
    }
    __syncthreads();
    if (tid < NROUTED) d_cnt2[tid] = 0;
}

__device__ __forceinline__ int tile_expert(int row0) {
    if (row0 < T_TOK) return 0;
    int e = 0;
#pragma unroll
    for (int j = 0; j < NROUTED; j++)
        if (row0 >= d_off[j] && row0 < d_off[j + 1]) e = j + 1;
    return e;
}

// ---------------- gemm1: 256 thr, 8 warps (2m x 4n), warp tile 64x32 -----------
// grid = (ntile, mtile): dead m-tiles occupy trailing bids -> shrink last wave
#define G1_STG  (3 * TILEB)
#define G1_SMEM (NSTAGE * G1_STG)        // 165888 B

__global__ __launch_bounds__(256, 1) void gemm1_kernel() {
    int row0 = blockIdx.y * BM;
    if (row0 >= d_off[7]) return;
    int e = tile_expert(row0);
    const __half* bg = d_wgT + (size_t)e * DFF * D_MODEL;
    const __half* bu = d_wuT + (size_t)e * DFF * D_MODEL;
    int n0 = blockIdx.x * 128;

    extern __shared__ char raw[];
    uint32_t base = smem_u32(raw);
    __shared__ int stok[128];
    __shared__ __align__(8) uint64_t s_mb[2 * NSTAGE];

    int tid = threadIdx.x, warp = tid >> 5, lane = tid & 31;
    if (tid < 128) stok[tid] = d_tok[row0 + tid];
    uint32_t mbF = smem_u32(&s_mb[0]);
    uint32_t mbE = smem_u32(&s_mb[NSTAGE]);
    if (tid < NSTAGE)              mbar_init(mbF + tid * 8, 8);
    else if (tid < 2 * NSTAGE)     mbar_init(mbE + (tid - NSTAGE) * 8, 8);
    __syncthreads();

    int wm = (warp >> 2) * 64, wn = (warp & 3) * 32;

    int ar[4], ac[4]; const __half* asrc[4]; const __half* gsrc[4]; const __half* usrc[4];
    bool apred[4];
#pragma unroll
    for (int i = 0; i < 4; i++) {
        int f = tid + i * 256;
        ar[i] = f >> 3; ac[i] = f & 7;
        int tok = stok[ar[i]];
        apred[i] = (tok >= 0);
        asrc[i] = d_X + (size_t)(apred[i] ? tok : 0) * D_MODEL + ac[i] * 8;
        gsrc[i] = bg + (size_t)(n0 + ar[i]) * D_MODEL + ac[i] * 8;
        usrc[i] = bu + (size_t)(n0 + ar[i]) * D_MODEL + ac[i] * 8;
    }

    auto issue = [&](int s, int ktile) {
        uint32_t S = base + s * G1_STG;
        int k0 = ktile * BK;
#pragma unroll
        for (int i = 0; i < 4; i++) {
            uint32_t d0 = S + ar[i] * ROWB + ac[i] * 16;
            cp16s(d0,             asrc[i] + (apred[i] ? k0 : 0), apred[i]);
            cp16s(d0 + TILEB,     gsrc[i] + k0, true);
            cp16s(d0 + 2 * TILEB, usrc[i] + k0, true);
        }
        cp_commit();
    };

    int arow = 8 * ((lane >> 3) & 1) + (lane & 7);
    int abyt = 16 * (lane >> 4);
    uint32_t aoff[4];
#pragma unroll
    for (int mi = 0; mi < 4; mi++)
        aoff[mi] = (uint32_t)((wm + mi * 16 + arow) * ROWB + abyt);
    int brow = 8 * (lane >> 4) + (lane & 7);
    int bbyt = 16 * ((lane >> 3) & 1);
    uint32_t goff[2], uoff[2];
#pragma unroll
    for (int p = 0; p < 2; p++) {
        uint32_t o = (uint32_t)((wn + p * 16 + brow) * ROWB + bbyt);
        goff[p] = TILEB + o;
        uoff[p] = 2 * TILEB + o;
    }

    float accG[4][4][4], accU[4][4][4];
#pragma unroll
    for (int mi = 0; mi < 4; mi++)
#pragma unroll
        for (int ni = 0; ni < 4; ni++)
#pragma unroll
            for (int r = 0; r < 4; r++) { accG[mi][ni][r] = 0.f; accU[mi][ni][r] = 0.f; }

    const int KT = D_MODEL / BK;   // 16
#pragma unroll
    for (int p = 0; p < NSTAGE; p++) issue(p, p);

    for (int kt = 0; kt < KT; kt++) {
        int s = kt % NSTAGE;
        uint32_t ph = (uint32_t)((kt / NSTAGE) & 1);
        uint32_t fB = mbF + s * 8, eB = mbE + s * 8;

        if (kt < KT - 2) cp_wait2(); else if (kt == KT - 2) cp_wait1(); else cp_wait0();
        __syncwarp();
        if (lane == 0) mbar_arrive(fB);
        mbar_wait(fB, ph);

        uint32_t S = base + s * G1_STG;
#pragma unroll
        for (int ks = 0; ks < 4; ks++) {
            uint32_t a[4][4];
#pragma unroll
            for (int mi = 0; mi < 4; mi++)
                LDSM4(a[mi][0], a[mi][1], a[mi][2], a[mi][3], S + aoff[mi] + ks * 32);
#pragma unroll
            for (int p = 0; p < 2; p++) {
                uint32_t g4[4], u4[4];
                LDSM4(g4[0], g4[1], g4[2], g4[3], S + goff[p] + ks * 32);
                LDSM4(u4[0], u4[1], u4[2], u4[3], S + uoff[p] + ks * 32);
#pragma unroll
                for (int mi = 0; mi < 4; mi++) {
                    hmma(accG[mi][2 * p],     a[mi], g4 + 0);
                    hmma(accG[mi][2 * p + 1], a[mi], g4 + 2);
                    hmma(accU[mi][2 * p],     a[mi], u4 + 0);
                    hmma(accU[mi][2 * p + 1], a[mi], u4 + 2);
                }
            }
        }
        __syncwarp();
        if (lane == 0) mbar_arrive(eB);

        if (kt + NSTAGE < KT) {
            mbar_wait(eB, ph);
            issue(s, kt + NSTAGE);
        }
    }

#pragma unroll
    for (int mi = 0; mi < 4; mi++)
#pragma unroll
        for (int ni = 0; ni < 4; ni++)
#pragma unroll
            for (int rr = 0; rr < 4; rr++) {
                int rl = wm + mi * 16 + (lane >> 2) + ((rr >= 2) ? 8 : 0);
                if (stok[rl] < 0) continue;
                int col = n0 + wn + ni * 8 + 2 * (lane & 3) + (rr & 1);
                float g = accG[mi][ni][rr], u = accU[mi][ni][rr];
                float h = (g / (1.f + __expf(-g))) * u;
                d_H[(size_t)(row0 + rl) * DFF + col] = __float2half_rn(h);
            }
}

// ---------------- gemm2: 256 thr, warp tile 64x32, down GEMM + scatter ---------
#define G2_STG  (2 * TILEB)
#define G2_SMEM (NSTAGE * G2_STG)        // 110592 B

__global__ __launch_bounds__(256, 1) void gemm2_kernel(float* __restrict__ out) {
    int row0 = blockIdx.y * BM;
    if (row0 >= d_off[7]) return;
    int e = tile_expert(row0);
    const __half* bw = d_wdT + (size_t)e * DFF * D_MODEL;
    int n0 = blockIdx.x * 128;

    extern __shared__ char raw[];
    uint32_t base = smem_u32(raw);
    __shared__ int stok[128];
    __shared__ float swt[128];
    __shared__ __align__(8) uint64_t s_mb[2 * NSTAGE];

    int tid = threadIdx.x, warp = tid >> 5, lane = tid & 31;
    if (tid < 128) { stok[tid] = d_tok[row0 + tid]; swt[tid] = d_wrow[row0 + tid]; }
    uint32_t mbF = smem_u32(&s_mb[0]);
    uint32_t mbE = smem_u32(&s_mb[NSTAGE]);
    if (tid < NSTAGE)              mbar_init(mbF + tid * 8, 8);
    else if (tid < 2 * NSTAGE)     mbar_init(mbE + (tid - NSTAGE) * 8, 8);
    __syncthreads();

    int wm = (warp >> 2) * 64, wn = (warp & 3) * 32;

    int ar[4], ac[4]; bool apred[4]; const __half* asrc[4]; const __half* bsrc[4];
#pragma unroll
    for (int i = 0; i < 4; i++) {
        int f = tid + i * 256;
        ar[i] = f >> 3; ac[i] = f & 7;
        apred[i] = (stok[ar[i]] >= 0);
        asrc[i] = d_H + (size_t)(row0 + ar[i]) * DFF + ac[i] * 8;
        bsrc[i] = bw + (size_t)(n0 + ar[i]) * DFF + ac[i] * 8;
    }

    auto issue = [&](int s, int ktile) {
        uint32_t S = base + s * G2_STG;
        int k0 = ktile * BK;
#pragma unroll
        for (int i = 0; i < 4; i++) {
            uint32_t d0 = S + ar[i] * ROWB + ac[i] * 16;
            cp16s(d0,         asrc[i] + (apred[i] ? k0 : 0), apred[i]);
            cp16s(d0 + TILEB, bsrc[i] + k0, true);
        }
        cp_commit();
    };

    int arow = 8 * ((lane >> 3) & 1) + (lane & 7);
    int abyt = 16 * (lane >> 4);
    uint32_t aoff[4];
#pragma unroll
    for (int mi = 0; mi < 4; mi++)
        aoff[mi] = (uint32_t)((wm + mi * 16 + arow) * ROWB + abyt);
    int brow = 8 * (lane >> 4) + (lane & 7);
    int bbyt = 16 * ((lane >> 3) & 1);
    uint32_t boff[2];
#pragma unroll
    for (int p = 0; p < 2; p++)
        boff[p] = TILEB + (uint32_t)((wn + p * 16 + brow) * ROWB + bbyt);

    float acc[4][4][4];
#pragma unroll
    for (int mi = 0; mi < 4; mi++)
#pragma unroll
        for (int ni = 0; ni < 4; ni++)
#pragma unroll
            for (int r = 0; r < 4; r++) acc[mi][ni][r] = 0.f;

    const int KT = DFF / BK;   // 32
#pragma unroll
    for (int p = 0; p < NSTAGE; p++) issue(p, p);

    for (int kt = 0; kt < KT; kt++) {
        int s = kt % NSTAGE;
        uint32_t ph = (uint32_t)((kt / NSTAGE) & 1);
        uint32_t fB = mbF + s * 8, eB = mbE + s * 8;

        if (kt < KT - 2) cp_wait2(); else if (kt == KT - 2) cp_wait1(); else cp_wait0();
        __syncwarp();
        if (lane == 0) mbar_arrive(fB);
        mbar_wait(fB, ph);

        uint32_t S = base + s * G2_STG;
#pragma unroll
        for (int ks = 0; ks < 4; ks++) {
            uint32_t a[4][4];
#pragma unroll
            for (int mi = 0; mi < 4; mi++)
                LDSM4(a[mi][0], a[mi][1], a[mi][2], a[mi][3], S + aoff[mi] + ks * 32);
#pragma unroll
            for (int p = 0; p < 2; p++) {
                uint32_t b4[4];
                LDSM4(b4[0], b4[1], b4[2], b4[3], S + boff[p] + ks * 32);
#pragma unroll
                for (int mi = 0; mi < 4; mi++) {
                    hmma(acc[mi][2 * p],     a[mi], b4 + 0);
                    hmma(acc[mi][2 * p + 1], a[mi], b4 + 2);
                }
            }
        }
        __syncwarp();
        if (lane == 0) mbar_arrive(eB);

        if (kt + NSTAGE < KT) {
            mbar_wait(eB, ph);
            issue(s, kt + NSTAGE);
        }
    }

#pragma unroll
    for (int mi = 0; mi < 4; mi++)
#pragma unroll
        for (int ni = 0; ni < 4; ni++)
#pragma unroll
            for (int rr = 0; rr < 4; rr++) {
                int rl = wm + mi * 16 + (lane >> 2) + ((rr >= 2) ? 8 : 0);
                int tok = stok[rl];
                if (tok < 0) continue;
                int col = n0 + wn + ni * 8 + 2 * (lane & 3) + (rr & 1);
                atomicAdd(out + (size_t)tok * D_MODEL + col, swt[rl] * acc[mi][ni][rr]);
            }
}

// ---------------- launch: R13 schedule, swizzled gemm grids --------------------
extern "C" void kernel_launch(void* const* d_in, const int* in_sizes, int n_in,
                              void* d_out, int out_size) {
    const float* x  = (const float*)d_in[0];
    const float* rw = (const float*)d_in[1];
    const float* rb = (const float*)d_in[2];
    const float* wg = (const float*)d_in[3];
    const float* wu = (const float*)d_in[4];
    const float* wd = (const float*)d_in[5];
    float* out = (float*)d_out;
    (void)in_sizes; (void)n_in; (void)out_size;

    static cudaStream_t s1 = nullptr;
    static cudaEvent_t evFork = nullptr, evGU = nullptr, evWd = nullptr;
    if (!s1) {
        cudaStreamCreateWithFlags(&s1, cudaStreamNonBlocking);
        cudaEventCreateWithFlags(&evFork, cudaEventDisableTiming);
        cudaEventCreateWithFlags(&evGU,   cudaEventDisableTiming);
        cudaEventCreateWithFlags(&evWd,   cudaEventDisableTiming);
        cudaFuncSetAttribute(gemm1_kernel, cudaFuncAttributeMaxDynamicSharedMemorySize, G1_SMEM);
        cudaFuncSetAttribute(gemm2_kernel, cudaFuncAttributeMaxDynamicSharedMemorySize, G2_SMEM);
    }

    cudaEventRecord(evFork, 0);
    cudaStreamWaitEvent(s1, evFork, 0);

    prep_wgu_kernel<<<8192, 256, 0, s1>>>(wg, wu);
    cudaEventRecord(evGU, s1);

    prep_x_kernel<<<1024, 256>>>(x, rw, rb, out);     // stream 0
    offsfill_kernel<<<1, 1024>>>();

    cudaStreamWaitEvent(0, evGU, 0);
    gemm1_kernel<<<dim3(DFF / 128, NTILES_M), 256, G1_SMEM>>>();   // 4th launch (ncu)

    prep_wd_kernel<<<4096, 256, 0, s1>>>(wd);         // overlaps gemm1
    cudaEventRecord(evWd, s1);

    cudaStreamWaitEvent(0, evWd, 0);
    gemm2_kernel<<<dim3(D_MODEL / 128, NTILES_M), 256, G2_SMEM>>>(out);
}

// round 17
// speedup vs baseline: 1.0460x; 1.0060x over previous
#include <cuda_runtime.h>
#include <cuda_fp16.h>
#include <cstdint>

// Problem constants
#define T_TOK   4096
#define D_MODEL 1024
#define DFF     2048
#define NROUTED 7
#define BM      128
#define BK      64
#define NTILES_M 104
#define R_MAX   (NTILES_M * BM)

// smem tile: 128 rows x 128B data (64 fp16), stride 144B -> conflict-free ldmatrix
#define ROWB   144
#define TILEB  (128 * ROWB)      // 18432 B
#define NSTAGE 3

// ---------------- scratch (static device globals; no allocations) -------------
__device__ __half d_H[(size_t)R_MAX * DFF];
__device__ __half d_X[(size_t)T_TOK * D_MODEL];
__device__ __half d_wgT[(size_t)8 * DFF * D_MODEL];   // [E][N=DFF][K=D]
__device__ __half d_wuT[(size_t)8 * DFF * D_MODEL];
__device__ __half d_wdT[(size_t)8 * D_MODEL * DFF];   // [E][N=D][K=DFF]
__device__ int    d_tok[R_MAX];
__device__ float  d_wrow[R_MAX];
__device__ int    d_off[8];
__device__ int    d_cnt[NROUTED];
__device__ int    d_cnt2[NROUTED];
__device__ int    d_topi[T_TOK * 2];
__device__ float  d_topw[T_TOK * 2];

// ---------------- helpers ----------------------------------------------------
__device__ __forceinline__ uint32_t smem_u32(const void* p) {
    uint32_t a;
    asm("{ .reg .u64 t; cvta.to.shared.u64 t, %1; cvt.u32.u64 %0, t; }"
        : "=r"(a) : "l"(p));
    return a;
}

__device__ __forceinline__ void hmma(float c[4], const uint32_t a[4], const uint32_t b[2]) {
    asm volatile(
        "mma.sync.aligned.m16n8k16.row.col.f32.f16.f16.f32 "
        "{%0,%1,%2,%3}, {%4,%5,%6,%7}, {%8,%9}, {%0,%1,%2,%3};\n"
        : "+f"(c[0]), "+f"(c[1]), "+f"(c[2]), "+f"(c[3])
        : "r"(a[0]), "r"(a[1]), "r"(a[2]), "r"(a[3]), "r"(b[0]), "r"(b[1]));
}

#define LDSM4(r0, r1, r2, r3, addr) \
    asm volatile("ldmatrix.sync.aligned.m8n8.x4.shared.b16 {%0,%1,%2,%3}, [%4];" \
                 : "=r"(r0), "=r"(r1), "=r"(r2), "=r"(r3) : "r"(addr))

__device__ __forceinline__ void cp16s(uint32_t daddr, const void* src, bool pred) {
    int sz = pred ? 16 : 0;
    asm volatile("cp.async.cg.shared.global [%0], [%1], 16, %2;\n"
                 :: "r"(daddr), "l"(src), "r"(sz));
}
__device__ __forceinline__ void cp_commit() { asm volatile("cp.async.commit_group;\n"); }
__device__ __forceinline__ void cp_wait2()  { asm volatile("cp.async.wait_group 2;\n"); }
__device__ __forceinline__ void cp_wait1()  { asm volatile("cp.async.wait_group 1;\n"); }
__device__ __forceinline__ void cp_wait0()  { asm volatile("cp.async.wait_group 0;\n"); }

__device__ __forceinline__ void mbar_init(uint32_t addr, uint32_t cnt) {
    asm volatile("mbarrier.init.shared.b64 [%0], %1;" :: "r"(addr), "r"(cnt) : "memory");
}
__device__ __forceinline__ void mbar_arrive(uint32_t addr) {
    asm volatile("mbarrier.arrive.shared.b64 _, [%0];" :: "r"(addr) : "memory");
}
__device__ __forceinline__ void mbar_wait(uint32_t addr, uint32_t parity) {
    asm volatile(
        "{\n\t.reg .pred P;\n\t"
        "W%=:\n\t"
        "mbarrier.try_wait.parity.acquire.cta.shared::cta.b64 P, [%0], %1, 0x989680;\n\t"
        "@!P bra W%=;\n\t}"
        :: "r"(addr), "r"(parity) : "memory");
}

// ---------------- coalesced transpose/convert: fp32 [R][C] -> fp16 [C][R] ------
__device__ __forceinline__ void tr_tile128(const float* __restrict__ s,
                                           __half* __restrict__ d,
                                           int R, int C, int r0, int c0) {
    __shared__ float t[128][33];
    int tid = threadIdx.x;
#pragma unroll
    for (int i = 0; i < 4; i++) {
        int ch = tid + i * 256;
        int r = ch >> 3, c4 = (ch & 7) * 4;
        float4 v = *(const float4*)(s + (size_t)(r0 + r) * C + c0 + c4);
        t[r][c4] = v.x; t[r][c4 + 1] = v.y; t[r][c4 + 2] = v.z; t[r][c4 + 3] = v.w;
    }
    __syncthreads();
#pragma unroll
    for (int i = 0; i < 2; i++) {
        int ch = tid + i * 256;
        int c = ch >> 4, q = ch & 15;
        __half h[8];
#pragma unroll
        for (int j = 0; j < 8; j++)
            h[j] = __float2half_rn(t[q * 8 + j][c]);
        *(uint4*)(d + (size_t)(c0 + c) * R + r0 + q * 8) = *(const uint4*)h;
    }
}

__global__ void prep_wgu_kernel(const float* __restrict__ wg,
                                const float* __restrict__ wu) {
    int b = blockIdx.x;                 // 8192 blocks
    int z = b >> 9;
    int ti = b & 511;
    int e = z & 7;
    const float* s = (z < 8) ? wg : wu;
    __half* d = ((z < 8) ? d_wgT : d_wuT);
    const int R = D_MODEL, C = DFF;
    int cx = ti & 63, ry = ti >> 6;
    tr_tile128(s + (size_t)e * R * C, d + (size_t)e * R * C, R, C, ry * 128, cx * 32);
}

__global__ void prep_wd_kernel(const float* __restrict__ wd) {
    int b = blockIdx.x;                 // 4096 blocks
    int e = b >> 9;
    int ti = b & 511;
    const int R = DFF, C = D_MODEL;
    int cx = ti & 31, ry = ti >> 5;
    tr_tile128(wd + (size_t)e * R * C, d_wdT + (size_t)e * R * C, R, C, ry * 128, cx * 32);
}

// ---------------- prep X: init + x convert + router (stream 0) -----------------
__global__ void prep_x_kernel(const float* __restrict__ x,
                              const float* __restrict__ rw,
                              const float* __restrict__ rb,
                              float* __restrict__ out) {
    int tid = threadIdx.x;
    int b = blockIdx.x;
    if (b < 512) {
        int warp = tid >> 5, lane = tid & 31;
        int gw = b * 8 + warp;
        const float* xr = x + (size_t)gw * D_MODEL;
        float acc[NROUTED];
#pragma unroll
        for (int j = 0; j < NROUTED; j++) acc[j] = 0.f;
        for (int k = lane; k < D_MODEL; k += 32) {
            float xv = xr[k];
            const float* w = rw + k * NROUTED;
#pragma unroll
            for (int j = 0; j < NROUTED; j++) acc[j] += xv * w[j];
        }
#pragma unroll
        for (int j = 0; j < NROUTED; j++) {
#pragma unroll
            for (int o = 16; o > 0; o >>= 1)
                acc[j] += __shfl_xor_sync(0xffffffffu, acc[j], o);
        }
        if (lane == 0) {
            float lg[NROUTED];
#pragma unroll
            for (int j = 0; j < NROUTED; j++) lg[j] = acc[j] + rb[j];
            int i1 = 0;
#pragma unroll
            for (int j = 1; j < NROUTED; j++) if (lg[j] > lg[i1]) i1 = j;
            int i2 = (i1 == 0) ? 1 : 0;
#pragma unroll
            for (int j = 0; j < NROUTED; j++)
                if (j != i1 && lg[j] > lg[i2]) i2 = j;
            float m  = fmaxf(lg[i1], lg[i2]);
            float e1 = expf(lg[i1] - m), e2 = expf(lg[i2] - m);
            float s  = e1 + e2;
            d_topi[gw * 2] = i1;  d_topi[gw * 2 + 1] = i2;
            d_topw[gw * 2] = e1 / s;  d_topw[gw * 2 + 1] = e2 / s;
            atomicAdd(&d_cnt[i1], 1);
            atomicAdd(&d_cnt[i2], 1);
        }
    }
    int stride = gridDim.x * blockDim.x;
    int i = b * blockDim.x + tid;
    for (int j = i; j < T_TOK * D_MODEL; j += stride) {
        out[j] = 0.f;
        d_X[j] = __float2half_rn(x[j]);
    }
    for (int j = i; j < R_MAX; j += stride) {
        if (j < T_TOK) { d_tok[j] = j;  d_wrow[j] = 1.f; }
        else           { d_tok[j] = -1; d_wrow[j] = 0.f; }
    }
}

// ---------------- offsets (1 warp) + parallel fill -----------------------------
__global__ void offsets_kernel() {
    if (threadIdx.x == 0) {
        int base = T_TOK;
        for (int j = 0; j < NROUTED; j++) {
            d_off[j] = base;
            base += ((d_cnt[j] + BM - 1) / BM) * BM;
            d_cnt[j] = 0;                 // reset for next replay
        }
        d_off[7] = base;
    }
}

__global__ void fill_kernel() {
    int i = blockIdx.x * blockDim.x + threadIdx.x;
    if (i < T_TOK * 2) {
        int t = i >> 1;
        int e = d_topi[i];
        float w = d_topw[i];
        int p = atomicAdd(&d_cnt2[e], 1);
        int r = d_off[e] + p;
        d_tok[r]  = t;
        d_wrow[r] = w;
    }
}

__global__ void reset_kernel() {
    if (threadIdx.x < NROUTED) d_cnt2[threadIdx.x] = 0;   // replay-safe
}

__device__ __forceinline__ int tile_expert(int row0) {
    if (row0 < T_TOK) return 0;
    int e = 0;
#pragma unroll
    for (int j = 0; j < NROUTED; j++)
        if (row0 >= d_off[j] && row0 < d_off[j + 1]) e = j + 1;
    return e;
}

// ---------------- gemm1: 256 thr, 8 warps (2m x 4n), warp tile 64x32 -----------
// grid = (ntile, mtile): dead m-tiles occupy trailing bids -> shrink last wave
#define G1_STG  (3 * TILEB)
#define G1_SMEM (NSTAGE * G1_STG)        // 165888 B

__global__ __launch_bounds__(256, 1) void gemm1_kernel() {
    int row0 = blockIdx.y * BM;
    if (row0 >= d_off[7]) return;
    int e = tile_expert(row0);
    const __half* bg = d_wgT + (size_t)e * DFF * D_MODEL;
    const __half* bu = d_wuT + (size_t)e * DFF * D_MODEL;
    int n0 = blockIdx.x * 128;

    extern __shared__ char raw[];
    uint32_t base = smem_u32(raw);
    __shared__ int stok[128];
    __shared__ __align__(8) uint64_t s_mb[2 * NSTAGE];

    int tid = threadIdx.x, warp = tid >> 5, lane = tid & 31;
    if (tid < 128) stok[tid] = d_tok[row0 + tid];
    uint32_t mbF = smem_u32(&s_mb[0]);
    uint32_t mbE = smem_u32(&s_mb[NSTAGE]);
    if (tid < NSTAGE)              mbar_init(mbF + tid * 8, 8);
    else if (tid < 2 * NSTAGE)     mbar_init(mbE + (tid - NSTAGE) * 8, 8);
    __syncthreads();

    int wm = (warp >> 2) * 64, wn = (warp & 3) * 32;

    int ar[4], ac[4]; const __half* asrc[4]; const __half* gsrc[4]; const __half* usrc[4];
    bool apred[4];
#pragma unroll
    for (int i = 0; i < 4; i++) {
        int f = tid + i * 256;
        ar[i] = f >> 3; ac[i] = f & 7;
        int tok = stok[ar[i]];
        apred[i] = (tok >= 0);
        asrc[i] = d_X + (size_t)(apred[i] ? tok : 0) * D_MODEL + ac[i] * 8;
        gsrc[i] = bg + (size_t)(n0 + ar[i]) * D_MODEL + ac[i] * 8;
        usrc[i] = bu + (size_t)(n0 + ar[i]) * D_MODEL + ac[i] * 8;
    }

    auto issue = [&](int s, int ktile) {
        uint32_t S = base + s * G1_STG;
        int k0 = ktile * BK;
#pragma unroll
        for (int i = 0; i < 4; i++) {
            uint32_t d0 = S + ar[i] * ROWB + ac[i] * 16;
            cp16s(d0,             asrc[i] + (apred[i] ? k0 : 0), apred[i]);
            cp16s(d0 + TILEB,     gsrc[i] + k0, true);
            cp16s(d0 + 2 * TILEB, usrc[i] + k0, true);
        }
        cp_commit();
    };

    int arow = 8 * ((lane >> 3) & 1) + (lane & 7);
    int abyt = 16 * (lane >> 4);
    uint32_t aoff[4];
#pragma unroll
    for (int mi = 0; mi < 4; mi++)
        aoff[mi] = (uint32_t)((wm + mi * 16 + arow) * ROWB + abyt);
    int brow = 8 * (lane >> 4) + (lane & 7);
    int bbyt = 16 * ((lane >> 3) & 1);
    uint32_t goff[2], uoff[2];
#pragma unroll
    for (int p = 0; p < 2; p++) {
        uint32_t o = (uint32_t)((wn + p * 16 + brow) * ROWB + bbyt);
        goff[p] = TILEB + o;
        uoff[p] = 2 * TILEB + o;
    }

    float accG[4][4][4], accU[4][4][4];
#pragma unroll
    for (int mi = 0; mi < 4; mi++)
#pragma unroll
        for (int ni = 0; ni < 4; ni++)
#pragma unroll
            for (int r = 0; r < 4; r++) { accG[mi][ni][r] = 0.f; accU[mi][ni][r] = 0.f; }

    const int KT = D_MODEL / BK;   // 16
#pragma unroll
    for (int p = 0; p < NSTAGE; p++) issue(p, p);

    for (int kt = 0; kt < KT; kt++) {
        int s = kt % NSTAGE;
        uint32_t ph = (uint32_t)((kt / NSTAGE) & 1);
        uint32_t fB = mbF + s * 8, eB = mbE + s * 8;

        if (kt < KT - 2) cp_wait2(); else if (kt == KT - 2) cp_wait1(); else cp_wait0();
        __syncwarp();
        if (lane == 0) mbar_arrive(fB);
        mbar_wait(fB, ph);

        uint32_t S = base + s * G1_STG;
#pragma unroll
        for (int ks = 0; ks < 4; ks++) {
            uint32_t a[4][4];
#pragma unroll
            for (int mi = 0; mi < 4; mi++)
                LDSM4(a[mi][0], a[mi][1], a[mi][2], a[mi][3], S + aoff[mi] + ks * 32);
#pragma unroll
            for (int p = 0; p < 2; p++) {
                uint32_t g4[4], u4[4];
                LDSM4(g4[0], g4[1], g4[2], g4[3], S + goff[p] + ks * 32);
                LDSM4(u4[0], u4[1], u4[2], u4[3], S + uoff[p] + ks * 32);
#pragma unroll
                for (int mi = 0; mi < 4; mi++) {
                    hmma(accG[mi][2 * p],     a[mi], g4 + 0);
                    hmma(accG[mi][2 * p + 1], a[mi], g4 + 2);
                    hmma(accU[mi][2 * p],     a[mi], u4 + 0);
                    hmma(accU[mi][2 * p + 1], a[mi], u4 + 2);
                }
            }
        }
        __syncwarp();
        if (lane == 0) mbar_arrive(eB);

        if (kt + NSTAGE < KT) {
            mbar_wait(eB, ph);
            issue(s, kt + NSTAGE);
        }
    }

#pragma unroll
    for (int mi = 0; mi < 4; mi++)
#pragma unroll
        for (int ni = 0; ni < 4; ni++)
#pragma unroll
            for (int rr = 0; rr < 4; rr++) {
                int rl = wm + mi * 16 + (lane >> 2) + ((rr >= 2) ? 8 : 0);
                if (stok[rl] < 0) continue;
                int col = n0 + wn + ni * 8 + 2 * (lane & 3) + (rr & 1);
                float g = accG[mi][ni][rr], u = accU[mi][ni][rr];
                float h = (g / (1.f + __expf(-g))) * u;
                d_H[(size_t)(row0 + rl) * DFF + col] = __float2half_rn(h);
            }
}

// ---------------- gemm2: 256 thr, warp tile 64x32, down GEMM + scatter ---------
#define G2_STG  (2 * TILEB)
#define G2_SMEM (NSTAGE * G2_STG)        // 110592 B

__global__ __launch_bounds__(256, 1) void gemm2_kernel(float* __restrict__ out) {
    int row0 = blockIdx.y * BM;
    if (row0 >= d_off[7]) return;
    int e = tile_expert(row0);
    const __half* bw = d_wdT + (size_t)e * DFF * D_MODEL;
    int n0 = blockIdx.x * 128;

    extern __shared__ char raw[];
    uint32_t base = smem_u32(raw);
    __shared__ int stok[128];
    __shared__ float swt[128];
    __shared__ __align__(8) uint64_t s_mb[2 * NSTAGE];

    int tid = threadIdx.x, warp = tid >> 5, lane = tid & 31;
    if (tid < 128) { stok[tid] = d_tok[row0 + tid]; swt[tid] = d_wrow[row0 + tid]; }
    uint32_t mbF = smem_u32(&s_mb[0]);
    uint32_t mbE = smem_u32(&s_mb[NSTAGE]);
    if (tid < NSTAGE)              mbar_init(mbF + tid * 8, 8);
    else if (tid < 2 * NSTAGE)     mbar_init(mbE + (tid - NSTAGE) * 8, 8);
    __syncthreads();

    int wm = (warp >> 2) * 64, wn = (warp & 3) * 32;

    int ar[4], ac[4]; bool apred[4]; const __half* asrc[4]; const __half* bsrc[4];
#pragma unroll
    for (int i = 0; i < 4; i++) {
        int f = tid + i * 256;
        ar[i] = f >> 3; ac[i] = f & 7;
        apred[i] = (stok[ar[i]] >= 0);
        asrc[i] = d_H + (size_t)(row0 + ar[i]) * DFF + ac[i] * 8;
        bsrc[i] = bw + (size_t)(n0 + ar[i]) * DFF + ac[i] * 8;
    }

    auto issue = [&](int s, int ktile) {
        uint32_t S = base + s * G2_STG;
        int k0 = ktile * BK;
#pragma unroll
        for (int i = 0; i < 4; i++) {
            uint32_t d0 = S + ar[i] * ROWB + ac[i] * 16;
            cp16s(d0,         asrc[i] + (apred[i] ? k0 : 0), apred[i]);
            cp16s(d0 + TILEB, bsrc[i] + k0, true);
        }
        cp_commit();
    };

    int arow = 8 * ((lane >> 3) & 1) + (lane & 7);
    int abyt = 16 * (lane >> 4);
    uint32_t aoff[4];
#pragma unroll
    for (int mi = 0; mi < 4; mi++)
        aoff[mi] = (uint32_t)((wm + mi * 16 + arow) * ROWB + abyt);
    int brow = 8 * (lane >> 4) + (lane & 7);
    int bbyt = 16 * ((lane >> 3) & 1);
    uint32_t boff[2];
#pragma unroll
    for (int p = 0; p < 2; p++)
        boff[p] = TILEB + (uint32_t)((wn + p * 16 + brow) * ROWB + bbyt);

    float acc[4][4][4];
#pragma unroll
    for (int mi = 0; mi < 4; mi++)
#pragma unroll
        for (int ni = 0; ni < 4; ni++)
#pragma unroll
            for (int r = 0; r < 4; r++) acc[mi][ni][r] = 0.f;

    const int KT = DFF / BK;   // 32
#pragma unroll
    for (int p = 0; p < NSTAGE; p++) issue(p, p);

    for (int kt = 0; kt < KT; kt++) {
        int s = kt % NSTAGE;
        uint32_t ph = (uint32_t)((kt / NSTAGE) & 1);
        uint32_t fB = mbF + s * 8, eB = mbE + s * 8;

        if (kt < KT - 2) cp_wait2(); else if (kt == KT - 2) cp_wait1(); else cp_wait0();
        __syncwarp();
        if (lane == 0) mbar_arrive(fB);
        mbar_wait(fB, ph);

        uint32_t S = base + s * G2_STG;
#pragma unroll
        for (int ks = 0; ks < 4; ks++) {
            uint32_t a[4][4];
#pragma unroll
            for (int mi = 0; mi < 4; mi++)
                LDSM4(a[mi][0], a[mi][1], a[mi][2], a[mi][3], S + aoff[mi] + ks * 32);
#pragma unroll
            for (int p = 0; p < 2; p++) {
                uint32_t b4[4];
                LDSM4(b4[0], b4[1], b4[2], b4[3], S + boff[p] + ks * 32);
#pragma unroll
                for (int mi = 0; mi < 4; mi++) {
                    hmma(acc[mi][2 * p],     a[mi], b4 + 0);
                    hmma(acc[mi][2 * p + 1], a[mi], b4 + 2);
                }
            }
        }
        __syncwarp();
        if (lane == 0) mbar_arrive(eB);

        if (kt + NSTAGE < KT) {
            mbar_wait(eB, ph);
            issue(s, kt + NSTAGE);
        }
    }

#pragma unroll
    for (int mi = 0; mi < 4; mi++)
#pragma unroll
        for (int ni = 0; ni < 4; ni++)
#pragma unroll
            for (int rr = 0; rr < 4; rr++) {
                int rl = wm + mi * 16 + (lane >> 2) + ((rr >= 2) ? 8 : 0);
                int tok = stok[rl];
                if (tok < 0) continue;
                int col = n0 + wn + ni * 8 + 2 * (lane & 3) + (rr & 1);
                atomicAdd(out + (size_t)tok * D_MODEL + col, swt[rl] * acc[mi][ni][rr]);
            }
}

// ---------------- launch ---------------------------------------------------------
extern "C" void kernel_launch(void* const* d_in, const int* in_sizes, int n_in,
                              void* d_out, int out_size) {
    const float* x  = (const float*)d_in[0];
    const float* rw = (const float*)d_in[1];
    const float* rb = (const float*)d_in[2];
    const float* wg = (const float*)d_in[3];
    const float* wu = (const float*)d_in[4];
    const float* wd = (const float*)d_in[5];
    float* out = (float*)d_out;
    (void)in_sizes; (void)n_in; (void)out_size;

    static cudaStream_t s1 = nullptr;
    static cudaEvent_t evFork = nullptr, evGU = nullptr, evWd = nullptr;
    if (!s1) {
        cudaStreamCreateWithFlags(&s1, cudaStreamNonBlocking);
        cudaEventCreateWithFlags(&evFork, cudaEventDisableTiming);
        cudaEventCreateWithFlags(&evGU,   cudaEventDisableTiming);
        cudaEventCreateWithFlags(&evWd,   cudaEventDisableTiming);
        cudaFuncSetAttribute(gemm1_kernel, cudaFuncAttributeMaxDynamicSharedMemorySize, G1_SMEM);
        cudaFuncSetAttribute(gemm2_kernel, cudaFuncAttributeMaxDynamicSharedMemorySize, G2_SMEM);
    }

    cudaEventRecord(evFork, 0);
    cudaStreamWaitEvent(s1, evFork, 0);

    prep_wgu_kernel<<<8192, 256, 0, s1>>>(wg, wu);
    cudaEventRecord(evGU, s1);

    prep_x_kernel<<<1024, 256>>>(x, rw, rb, out);     // stream 0
    offsets_kernel<<<1, 32>>>();
    fill_kernel<<<32, 256>>>();
    reset_kernel<<<1, 32>>>();

    cudaStreamWaitEvent(0, evGU, 0);
    gemm1_kernel<<<dim3(DFF / 128, NTILES_M), 256, G1_SMEM>>>();

    prep_wd_kernel<<<4096, 256, 0, s1>>>(wd);         // overlaps gemm1
    cudaEventRecord(evWd, s1);

    cudaStreamWaitEvent(0, evWd, 0);
    gemm2_kernel<<<dim3(D_MODEL / 128, NTILES_M), 256, G2_SMEM>>>(out);
}